// round 14
// baseline (speedup 1.0000x reference)
#include <cuda_runtime.h>

#define DD      262144     // 512*512
#define NB      128        // batch
#define NENV    4
#define KSEL    26214      // floor(0.1 * 512 * 512)
#define NBIN    65536
#define NCRS    1024       // coarse bins = fkey >> 22
#define CANDMAX 16384      // boundary-bin candidate cap (expected ~4-30)

// Scratch (allocation-free: __device__ globals, zero-initialized at module load)
__device__ float    g_M[NENV][DD];        // per-env logits (written by rep blocks)
__device__ unsigned g_hist[NENV][NBIN];   // fine hist (hi 16 bits)
__device__ unsigned g_coarse[NENV][NCRS]; // coarse chunk sums (fkey>>22)
__device__ unsigned g_cand[NENV][CANDMAX];// boundary-bin candidate keys
__device__ int      g_ncand[NENV];
__device__ int      g_rep[NENV];          // first batch row of each env
__device__ unsigned g_binhi[NENV];
__device__ unsigned g_rank[NENV];         // rank within boundary bin (1-based)
__device__ unsigned g_kth[NENV];          // exact key of k-th largest per env

// Monotone mapping: float total order -> unsigned total order
__device__ __forceinline__ unsigned fkey(float f) {
    unsigned u = __float_as_uint(f);
    return (u & 0x80000000u) ? ~u : (u | 0x80000000u);
}
__device__ __forceinline__ float sigm(float x) {
    return __fdividef(1.0f, 1.0f + __expf(-x));   // MUFU EX2 + fast RCP
}
__device__ __forceinline__ float4 madd(float4 a, float4 b) {
    float4 m; m.x = a.x + b.x; m.y = a.y + b.y; m.z = a.z + b.z; m.w = a.w + b.w;
    return m;
}

// Representative row per env (first occurrence) + candidate-counter reset.
__global__ void k_rep(const int* __restrict__ env_idx) {
    int t = threadIdx.x;                       // blockDim = NB
    if (t < NENV) { g_rep[t] = 0x7FFFFFFF; g_ncand[t] = 0; }
    __syncthreads();
    atomicMin(&g_rep[env_idx[t]], t);
}

// L + S writer for all rows; the representative block of each env additionally
// stores g_M and accumulates the fine hist + smem coarse sums. The rep branch
// is uniform per block (b identical blockwide), so its __syncthreads is legal.
// Requires g_hist/g_coarse == 0 on entry (load-time zero; re-zeroed by k_gather).
__global__ void k_outLS(const int* __restrict__ env_idx,
                        float* __restrict__ outL, float* __restrict__ outS,
                        const float* __restrict__ base, const float* __restrict__ deltas) {
    __shared__ unsigned sc[NCRS];
    int b = blockIdx.y;
    int t = threadIdx.x;
    int e = __ldg(&env_idx[b]);
    bool isrep = (g_rep[e] == b);
    if (isrep) {
        sc[t] = 0u; sc[t + 256] = 0u; sc[t + 512] = 0u; sc[t + 768] = 0u;
        __syncthreads();
    }
    size_t i = ((size_t)blockIdx.x * 256 + t) * 4;
    float4 m = madd(*(const float4*)(base + i),
                    *(const float4*)(deltas + (size_t)e * DD + i));
    float4 s;
    s.x = sigm(m.x); s.y = sigm(m.y); s.z = sigm(m.z); s.w = sigm(m.w);
    size_t off = (size_t)b * DD + i;
    *(float4*)(outL + off) = m;
    *(float4*)(outS + off) = s;
    if (isrep) {
        *(float4*)(&g_M[e][i]) = m;
        unsigned k0 = fkey(m.x), k1 = fkey(m.y), k2 = fkey(m.z), k3 = fkey(m.w);
        atomicAdd(&g_hist[e][k0 >> 16], 1u);
        atomicAdd(&g_hist[e][k1 >> 16], 1u);
        atomicAdd(&g_hist[e][k2 >> 16], 1u);
        atomicAdd(&g_hist[e][k3 >> 16], 1u);
        atomicAdd(&sc[k0 >> 22], 1u);
        atomicAdd(&sc[k1 >> 22], 1u);
        atomicAdd(&sc[k2 >> 22], 1u);
        atomicAdd(&sc[k3 >> 22], 1u);
        __syncthreads();
        #pragma unroll
        for (int j = 0; j < 4; j++) {
            unsigned v = sc[t + j * 256];
            if (v) atomicAdd(&g_coarse[e][t + j * 256], v);
        }
    }
}

// Warp-shuffle suffix scan over the 1024 coarse sums -> boundary chunk, then
// serial walk of its 64 fine bins -> (binhi, rank within bin). 2 barrier rounds.
__global__ void k_scan0() {
    int e = blockIdx.x;
    int t = threadIdx.x;                       // 1024
    int lane = t & 31, w = t >> 5;
    __shared__ unsigned wt[32], sf[32];
    __shared__ unsigned sel[2];
    __shared__ unsigned bins64[64];
    if (t == 0) { sel[0] = 0u; sel[1] = 0u; }  // guard (absent env -> benign)

    unsigned own = g_coarse[e][t];
    unsigned v = own;                          // within-warp inclusive suffix
    #pragma unroll
    for (int off = 1; off < 32; off <<= 1) {
        unsigned x = __shfl_down_sync(0xFFFFFFFFu, v, off);
        if (lane + off < 32) v += x;
    }
    if (lane == 0) wt[w] = v;                  // warp totals
    __syncthreads();
    if (w == 0) {
        unsigned u = wt[lane];                 // inclusive suffix over warps
        #pragma unroll
        for (int off = 1; off < 32; off <<= 1) {
            unsigned x = __shfl_down_sync(0xFFFFFFFFu, u, off);
            if (lane + off < 32) u += x;
        }
        sf[lane] = u;
    }
    __syncthreads();
    unsigned tails = (w < 31) ? sf[w + 1] : 0u;
    unsigned ss = v + tails;                   // inclusive suffix at t
    unsigned above = ss - own;
    if (ss >= (unsigned)KSEL && above < (unsigned)KSEL) { sel[0] = (unsigned)t; sel[1] = above; }
    __syncthreads();

    unsigned cstar = sel[0], cum0 = sel[1];
    if (w == 0) {
        bins64[lane]      = g_hist[e][cstar * 64 + lane];
        bins64[lane + 32] = g_hist[e][cstar * 64 + 32 + lane];
    }
    __syncthreads();
    if (t == 0) {
        unsigned cum = cum0;
        unsigned bin = cstar * 64;
        for (int j = 63; j >= 0; j--) {
            unsigned vv = bins64[j];
            if (cum + vv >= (unsigned)KSEL) { bin = cstar * 64 + j; break; }
            cum += vv;
        }
        g_binhi[e] = bin;
        g_rank[e]  = (unsigned)KSEL - cum;     // >= 1
    }
}

// Gather boundary-bin candidates from g_M; also re-zeroes g_hist/g_coarse
// (coalesced, 1 word/thread) so the next graph replay starts clean.
__global__ void k_gather() {
    int e = blockIdx.y;
    unsigned hi = g_binhi[e];
    int tid = blockIdx.x * 256 + threadIdx.x;  // 0..65535 per env
    (&g_hist[0][0])[e * NBIN + tid] = 0u;
    if (tid < NCRS) g_coarse[e][tid] = 0u;
    int i = tid * 4;
    float4 m = *(const float4*)(&g_M[e][i]);
    unsigned k0 = fkey(m.x), k1 = fkey(m.y), k2 = fkey(m.z), k3 = fkey(m.w);
    if ((k0 >> 16) == hi) { int p = atomicAdd(&g_ncand[e], 1); if (p < CANDMAX) g_cand[e][p] = k0; }
    if ((k1 >> 16) == hi) { int p = atomicAdd(&g_ncand[e], 1); if (p < CANDMAX) g_cand[e][p] = k1; }
    if ((k2 >> 16) == hi) { int p = atomicAdd(&g_ncand[e], 1); if (p < CANDMAX) g_cand[e][p] = k2; }
    if ((k3 >> 16) == hi) { int p = atomicAdd(&g_ncand[e], 1); if (p < CANDMAX) g_cand[e][p] = k3; }
}

// Exact r-th largest among candidates by rank counting (order-independent ->
// deterministic despite nondeterministic gather order). Distinct keys assumed
// (continuous random floats): unique element has exactly r-1 keys above it.
__global__ void k_pick() {
    __shared__ unsigned scache[4096];
    int e = blockIdx.x;
    int t = threadIdx.x;                       // 256
    int n = g_ncand[e]; if (n > CANDMAX) n = CANDMAX;
    unsigned r = g_rank[e];
    int nc = (n < 4096) ? n : 4096;
    for (int j = t; j < nc; j += 256) scache[j] = g_cand[e][j];
    __syncthreads();
    for (int idx = t; idx < n; idx += 256) {
        unsigned x = (idx < 4096) ? scache[idx] : g_cand[e][idx];
        unsigned c = 0;
        for (int j = 0; j < nc; j++)   c += (scache[j] > x);
        for (int j = nc; j < n; j++)   c += (g_cand[e][j] > x);
        if (c == r - 1) g_kth[e] = x;
    }
}

// A writer: reads g_M (16 B/elem, half the LTS traffic of base+deltas). 134 MB.
__global__ void k_outA(const int* __restrict__ env_idx, float* __restrict__ outA) {
    int b = blockIdx.y;
    int e = __ldg(&env_idx[b]);
    unsigned kth = g_kth[e];
    size_t i = ((size_t)blockIdx.x * 256 + threadIdx.x) * 4;
    float4 m = *(const float4*)(&g_M[e][i]);
    float4 a;
    a.x = (fkey(m.x) >= kth) ? sigm(m.x) : 0.0f;
    a.y = (fkey(m.y) >= kth) ? sigm(m.y) : 0.0f;
    a.z = (fkey(m.z) >= kth) ? sigm(m.z) : 0.0f;
    a.w = (fkey(m.w) >= kth) ? sigm(m.w) : 0.0f;
    *(float4*)(outA + (size_t)b * DD + i) = a;
}

extern "C" void kernel_launch(void* const* d_in, const int* in_sizes, int n_in,
                              void* d_out, int out_size) {
    const float* base   = nullptr;
    const float* deltas = nullptr;
    const int*   env    = nullptr;
    for (int i = 0; i < n_in; i++) {
        if      (in_sizes[i] == DD)        base   = (const float*)d_in[i];
        else if (in_sizes[i] == NENV * DD) deltas = (const float*)d_in[i];
        else if (in_sizes[i] == NB)        env    = (const int*)d_in[i];
        // z_s (131072 elems) unused by the reference outputs
    }

    float* outA = (float*)d_out;            // tuple order: (A, A_logits, A_soft)
    float* outL = outA + (size_t)NB * DD;
    float* outS = outL + (size_t)NB * DD;

    dim3 go(DD / 1024, NB);                 // (256, 128)
    dim3 gb(DD / 1024, NENV);               // (256, 4)

    k_rep<<<1, NB>>>(env);
    k_outLS<<<go, 256>>>(env, outL, outS, base, deltas);
    k_scan0<<<NENV, 1024>>>();
    k_gather<<<gb, 256>>>();
    k_pick<<<NENV, 256>>>();
    k_outA<<<go, 256>>>(env, outA);
}